// round 2
// baseline (speedup 1.0000x reference)
#include <cuda_runtime.h>
#include <math.h>
#include <stdint.h>

#define N_NODES 5000
#define B_SZ    16
#define F_INDIM 32
#define D_DIM   64
#define E_EDGES 80000
#define NNZ     (E_EDGES + N_NODES)
#define K_OBS   (N_NODES * D_DIM)          // 320000

// ----- scratch (device globals; no allocation allowed) -----
__device__ int   g_deg[N_NODES];
__device__ float g_dinv[N_NODES];
__device__ int   g_off[N_NODES + 1];
__device__ int   g_cur[N_NODES];
__device__ int   g_esrc[NNZ];
__device__ int   g_eid[NNZ];
__device__ float g_ew[NNZ];
__device__ float g_XT[N_NODES * F_INDIM * B_SZ];     // [n][f][b]
__device__ float g_H1[N_NODES * D_DIM * B_SZ];       // [n][d][b]
__device__ float g_OBS[N_NODES * D_DIM * B_SZ];      // [k][b], k = n*64+d
__device__ float g_part[300 * 2048];                 // per-block GEMM partials
__device__ float g_h1act[16 * 320];                  // tanh(layer1): C(1024) A(2048) B(2048)
__device__ float g_ha2[16 * 128];
__device__ float g_hb2[16 * 128];

// =================== graph preprocessing ===================
__global__ void k_init() {
    int i = blockIdx.x * blockDim.x + threadIdx.x;
    if (i < N_NODES) { g_deg[i] = 1; g_cur[i] = 0; }   // self-loop counted
}

__global__ void k_deg(const int* __restrict__ ei, int E) {
    int e = blockIdx.x * blockDim.x + threadIdx.x;
    if (e < E) atomicAdd(&g_deg[ei[E + e]], 1);        // dst = ei[1][e]
}

__global__ void k_dinv() {
    int i = blockIdx.x * blockDim.x + threadIdx.x;
    if (i < N_NODES) g_dinv[i] = rsqrtf((float)g_deg[i]);
}

// exclusive prefix sum of g_deg -> g_off (single block, 1024 threads)
__global__ void k_scan(int total) {
    __shared__ int s[1024];
    __shared__ int carry;
    int tid = threadIdx.x;
    if (tid == 0) carry = 0;
    __syncthreads();
    for (int base = 0; base < N_NODES; base += 1024) {
        int idx = base + tid;
        int v = (idx < N_NODES) ? g_deg[idx] : 0;
        s[tid] = v;
        __syncthreads();
        for (int o = 1; o < 1024; o <<= 1) {
            int t = (tid >= o) ? s[tid - o] : 0;
            __syncthreads();
            s[tid] += t;
            __syncthreads();
        }
        if (idx < N_NODES) g_off[idx] = carry + s[tid] - v;
        __syncthreads();
        if (tid == 0) carry += s[1023];
        __syncthreads();
    }
    if (tid == 0) g_off[N_NODES] = total;
}

__global__ void k_fill(const int* __restrict__ ei, int E) {
    int e = blockIdx.x * blockDim.x + threadIdx.x;
    if (e < E) {
        int s = ei[e], d = ei[E + e];
        int pos = g_off[d] + atomicAdd(&g_cur[d], 1);
        g_esrc[pos] = s;
        g_eid[pos]  = e;
        g_ew[pos] = g_dinv[s] * g_dinv[d];
    } else if (e < E + N_NODES) {
        int n = e - E;
        int pos = g_off[n] + atomicAdd(&g_cur[n], 1);
        g_esrc[pos] = n;
        g_eid[pos]  = e;
        g_ew[pos] = g_dinv[n] * g_dinv[n];
    }
}

// deterministic edge order within each row (insertion sort by original edge id)
__global__ void k_sortrows() {
    int n = blockIdx.x * blockDim.x + threadIdx.x;
    if (n >= N_NODES) return;
    int beg = g_off[n], end = g_off[n + 1];
    for (int i = beg + 1; i < end; i++) {
        int   id = g_eid[i], sr = g_esrc[i];
        float w  = g_ew[i];
        int j = i - 1;
        while (j >= beg && g_eid[j] > id) {
            g_eid[j + 1]  = g_eid[j];
            g_esrc[j + 1] = g_esrc[j];
            g_ew[j + 1]   = g_ew[j];
            j--;
        }
        g_eid[j + 1] = id; g_esrc[j + 1] = sr; g_ew[j + 1] = w;
    }
}

// transpose x [B,N,32] -> XT [n][f][b]
__global__ void k_xt(const float* __restrict__ x) {
    __shared__ float s[F_INDIM * 17];
    int n = blockIdx.x, t = threadIdx.x;       // 512 threads
    int b = t >> 5, f = t & 31;
    s[f * 17 + b] = x[(b * N_NODES + n) * F_INDIM + f];
    __syncthreads();
    int fo = t >> 4, bo = t & 15;
    g_XT[n * 512 + t] = s[fo * 17 + bo];
}

// =================== GCN layer 1 (agg in 32-dim, then W1, tanh) ===================
__global__ void k_gcn1(const float* __restrict__ W1, const float* __restrict__ b1) {
    __shared__ float sW[F_INDIM * D_DIM];   // 2048
    __shared__ float sAgg[512];
    __shared__ int   sSrc[128];
    __shared__ float sWt[128];
    int n = blockIdx.x, tid = threadIdx.x;  // 512 threads
    for (int i = tid; i < 2048; i += 512) sW[i] = W1[i];

    int beg = g_off[n], end = g_off[n + 1];
    float a0 = 0.f, a1 = 0.f, a2 = 0.f, a3 = 0.f;
    for (int p = beg; p < end;) {
        int cnt = min(128, end - p);
        if (tid < cnt) { sSrc[tid] = g_esrc[p + tid]; sWt[tid] = g_ew[p + tid]; }
        __syncthreads();
        int i = 0;
        for (; i + 4 <= cnt; i += 4) {
            a0 += sWt[i]     * g_XT[sSrc[i]     * 512 + tid];
            a1 += sWt[i + 1] * g_XT[sSrc[i + 1] * 512 + tid];
            a2 += sWt[i + 2] * g_XT[sSrc[i + 2] * 512 + tid];
            a3 += sWt[i + 3] * g_XT[sSrc[i + 3] * 512 + tid];
        }
        for (; i < cnt; i++) a0 += sWt[i] * g_XT[sSrc[i] * 512 + tid];
        p += cnt;
        __syncthreads();
    }
    sAgg[tid] = a0 + a1 + a2 + a3;
    __syncthreads();

    int b = tid & 15, d = tid >> 4;          // d in 0..31, also d+32
    float h0 = b1[d], h1 = b1[d + 32];
    #pragma unroll
    for (int f = 0; f < F_INDIM; f++) {
        float xa = sAgg[f * 16 + b];
        h0 += xa * sW[f * 64 + d];
        h1 += xa * sW[f * 64 + d + 32];
    }
    g_H1[(n * 64 + d) * 16 + b]        = tanhf(h0);
    g_H1[(n * 64 + d + 32) * 16 + b]   = tanhf(h1);
}

// =================== GCN layer 2 (agg in 64-dim, then W2, tanh -> OBS^T) ===================
__global__ void k_gcn2(const float* __restrict__ W2, const float* __restrict__ b2) {
    __shared__ float sW[D_DIM * D_DIM];     // 4096 = 16KB
    __shared__ float sAgg[1024];
    __shared__ int   sSrc[128];
    __shared__ float sWt[128];
    int n = blockIdx.x, tid = threadIdx.x;  // 512 threads
    for (int i = tid; i < 4096; i += 512) sW[i] = W2[i];

    int beg = g_off[n], end = g_off[n + 1];
    float lo0 = 0.f, lo1 = 0.f, hi0 = 0.f, hi1 = 0.f;
    for (int p = beg; p < end;) {
        int cnt = min(128, end - p);
        if (tid < cnt) { sSrc[tid] = g_esrc[p + tid]; sWt[tid] = g_ew[p + tid]; }
        __syncthreads();
        int i = 0;
        for (; i + 2 <= cnt; i += 2) {
            int s0 = sSrc[i] * 1024, s1 = sSrc[i + 1] * 1024;
            float w0 = sWt[i], w1 = sWt[i + 1];
            lo0 += w0 * g_H1[s0 + tid];
            hi0 += w0 * g_H1[s0 + 512 + tid];
            lo1 += w1 * g_H1[s1 + tid];
            hi1 += w1 * g_H1[s1 + 512 + tid];
        }
        if (i < cnt) {
            int s0 = sSrc[i] * 1024; float w0 = sWt[i];
            lo0 += w0 * g_H1[s0 + tid];
            hi0 += w0 * g_H1[s0 + 512 + tid];
        }
        p += cnt;
        __syncthreads();
    }
    sAgg[tid]       = lo0 + lo1;
    sAgg[tid + 512] = hi0 + hi1;
    __syncthreads();

    int b = tid & 15, d = tid >> 4;          // d in 0..31, also d+32
    float h0 = b2[d], h1 = b2[d + 32];
    #pragma unroll
    for (int dd = 0; dd < D_DIM; dd++) {
        float xa = sAgg[dd * 16 + b];
        h0 += xa * sW[dd * 64 + d];
        h1 += xa * sW[dd * 64 + d + 32];
    }
    g_OBS[(n * 64 + d) * 16 + b]      = tanhf(h0);
    g_OBS[(n * 64 + d + 32) * 16 + b] = tanhf(h1);
}

// =================== big GEMM: obs^T[320000][16] x {Wc1,Wa1,Wb1} ===================
// grid.x = 300: [0,50)=Wc1(64 cols, 6400 rows/blk), [50,175)=Wa1, [175,300)=Wb1 (128 cols, 2560 rows/blk)
__global__ void __launch_bounds__(128) k_big(const float* __restrict__ Wc,
                                             const float* __restrict__ Wa,
                                             const float* __restrict__ Wb) {
    __shared__ float sObs[128 * 16];                  // 8KB row stage
    unsigned long long* sObs64 = (unsigned long long*)sObs;

    int blk = blockIdx.x;
    const float* W; int ncols, segBlk, rows;
    if (blk < 50)       { W = Wc; ncols = 64;  segBlk = blk;       rows = 6400; }
    else if (blk < 175) { W = Wa; ncols = 128; segBlk = blk - 50;  rows = 2560; }
    else                { W = Wb; ncols = 128; segBlk = blk - 175; rows = 2560; }
    int k0 = segBlk * rows;

    const int tpr = ncols >> 2;        // threads covering one row: 16 or 32
    const int rpw = 32 / tpr;          // rows per warp step: 2 or 1
    int tid = threadIdx.x;
    int lane = tid & 31, w = tid >> 5;
    int slot = lane % tpr;             // column group (4 cols)
    int rr   = lane / tpr;

    unsigned long long acc[32];        // [c(4)][bpair(8)] f32x2
    #pragma unroll
    for (int i = 0; i < 32; i++) acc[i] = 0ULL;

    int iters = (rpw == 1) ? 32 : 16;
    for (int kt = k0; kt < k0 + rows; kt += 128) {
        const float4* src = (const float4*)(g_OBS + (size_t)kt * 16);
        float4* dst4 = (float4*)sObs;
        #pragma unroll
        for (int i = tid; i < 512; i += 128) dst4[i] = src[i];
        __syncthreads();

        for (int it = 0; it < iters; it++) {
            int r = (it * 4 + w) * rpw + rr;              // 0..127
            int k = kt + r;
            const float4 w4 = *(const float4*)(W + (size_t)k * ncols + slot * 4);
            unsigned long long wp0, wp1, wp2, wp3;
            asm("mov.b64 %0,{%1,%2};" : "=l"(wp0) : "f"(w4.x), "f"(w4.x));
            asm("mov.b64 %0,{%1,%2};" : "=l"(wp1) : "f"(w4.y), "f"(w4.y));
            asm("mov.b64 %0,{%1,%2};" : "=l"(wp2) : "f"(w4.z), "f"(w4.z));
            asm("mov.b64 %0,{%1,%2};" : "=l"(wp3) : "f"(w4.w), "f"(w4.w));
            const unsigned long long* ob = sObs64 + r * 8;
            #pragma unroll
            for (int p = 0; p < 8; p++) {
                unsigned long long o = ob[p];
                asm("fma.rn.f32x2 %0,%1,%2,%0;" : "+l"(acc[p])      : "l"(wp0), "l"(o));
                asm("fma.rn.f32x2 %0,%1,%2,%0;" : "+l"(acc[8 + p])  : "l"(wp1), "l"(o));
                asm("fma.rn.f32x2 %0,%1,%2,%0;" : "+l"(acc[16 + p]) : "l"(wp2), "l"(o));
                asm("fma.rn.f32x2 %0,%1,%2,%0;" : "+l"(acc[24 + p]) : "l"(wp3), "l"(o));
            }
        }
        __syncthreads();
    }

    // epilogue: reduce (4 warps x rpw row-groups) -> g_part[blk]
    for (int c = 0; c < 4; c++) {
        __syncthreads();
        #pragma unroll
        for (int p = 0; p < 8; p++) sObs64[tid * 8 + p] = acc[c * 8 + p];
        __syncthreads();
        for (int rid = tid; rid < tpr * 16; rid += 128) {
            int cslot = rid % tpr;
            int b = rid / tpr;
            float s = 0.f;
            for (int ww = 0; ww < 4; ww++)
                for (int r2 = 0; r2 < rpw; r2++)
                    s += sObs[(ww * 32 + r2 * tpr + cslot) * 16 + b];
            g_part[blk * 2048 + b * ncols + cslot * 4 + c] = s;
        }
    }
}

// reduce partials + bias + tanh -> g_h1act (5120 values)
__global__ void k_reduce(const float* __restrict__ bc1, const float* __restrict__ ba1,
                         const float* __restrict__ bb1) {
    int i = blockIdx.x * blockDim.x + threadIdx.x;
    if (i >= 5120) return;
    int blkBase, nblk, idx; float bias;
    if (i < 1024)      { blkBase = 0;   nblk = 50;  idx = i;        bias = bc1[i & 63]; }
    else if (i < 3072) { blkBase = 50;  nblk = 125; idx = i - 1024; bias = ba1[(i - 1024) & 127]; }
    else               { blkBase = 175; nblk = 125; idx = i - 3072; bias = bb1[(i - 3072) & 127]; }
    float s = bias;
    for (int q = 0; q < nblk; q++) s += g_part[(blkBase + q) * 2048 + idx];
    g_h1act[i] = tanhf(s);
}

// small middle MLP layers: block0 critic (-> out[240000..]), block1 alpha, block2 beta
__global__ void k_mid(const float* __restrict__ Wc2, const float* __restrict__ bc2,
                      const float* __restrict__ Wc3, const float* __restrict__ bc3,
                      const float* __restrict__ Wa2, const float* __restrict__ ba2,
                      const float* __restrict__ Wb2, const float* __restrict__ bb2,
                      float* __restrict__ out) {
    __shared__ float sH[2048];
    __shared__ float sH2[1024];
    int tid = threadIdx.x;               // 128 threads
    if (blockIdx.x == 0) {
        for (int i = tid; i < 1024; i += 128) sH[i] = g_h1act[i];
        __syncthreads();
        if (tid < 64) {
            int j = tid;
            float acc[16];
            #pragma unroll
            for (int b = 0; b < 16; b++) acc[b] = bc2[j];
            for (int k = 0; k < 64; k++) {
                float wv = Wc2[k * 64 + j];
                #pragma unroll
                for (int b = 0; b < 16; b++) acc[b] += sH[b * 64 + k] * wv;
            }
            #pragma unroll
            for (int b = 0; b < 16; b++) sH2[b * 64 + j] = tanhf(acc[b]);
        }
        __syncthreads();
        if (tid < 16) {
            float v = bc3[0];
            for (int j = 0; j < 64; j++) v += sH2[tid * 64 + j] * Wc3[j];
            out[240000 + tid] = v;
        }
    } else {
        const float* h1  = g_h1act + (blockIdx.x == 1 ? 1024 : 3072);
        const float* W2m = (blockIdx.x == 1 ? Wa2 : Wb2);
        const float* b2m = (blockIdx.x == 1 ? ba2 : bb2);
        float* dst       = (blockIdx.x == 1 ? g_ha2 : g_hb2);
        for (int i = tid; i < 2048; i += 128) sH[i] = h1[i];
        __syncthreads();
        int j = tid;                      // 128 threads = 128 cols
        float acc[16];
        #pragma unroll
        for (int b = 0; b < 16; b++) acc[b] = b2m[j];
        for (int k = 0; k < 128; k++) {
            float wv = W2m[k * 128 + j];
            #pragma unroll
            for (int b = 0; b < 16; b++) acc[b] += sH[b * 128 + k] * wv;
        }
        #pragma unroll
        for (int b = 0; b < 16; b++) dst[b * 128 + j] = tanhf(acc[b]);
    }
}

// =================== heads + Beta distribution ===================
__device__ __forceinline__ float softplus_f(float z) {
    return fmaxf(z, 0.f) + log1pf(expf(-fabsf(z)));
}
__device__ __forceinline__ float psi_f(float x) {
    // digamma for x >= 1 (alpha,beta >= 1): shift to >= 6, asymptotic series
    float r = 0.f;
    while (x < 6.f) { r -= 1.f / x; x += 1.f; }
    float xi = 1.f / x, xi2 = xi * xi;
    return r + logf(x) - 0.5f * xi
         - xi2 * (0.08333333333f - xi2 * (0.008333333333f - xi2 * 0.003968253968f));
}

__global__ void __launch_bounds__(128) k_final(const float* __restrict__ Wa3, const float* __restrict__ ba3,
                                               const float* __restrict__ Wb3, const float* __restrict__ bb3,
                                               float* __restrict__ out) {
    __shared__ float sA[2048], sB[2048];
    int tid = threadIdx.x;
    for (int i = tid; i < 2048; i += 128) { sA[i] = g_ha2[i]; sB[i] = g_hb2[i]; }
    __syncthreads();
    int n = blockIdx.x * 128 + tid;
    if (n >= N_NODES) return;

    float aA[16], aB[16];
    #pragma unroll
    for (int b = 0; b < 16; b++) { aA[b] = 0.f; aB[b] = 0.f; }
    for (int j = 0; j < 128; j++) {
        float wa = Wa3[j * N_NODES + n];
        float wb = Wb3[j * N_NODES + n];
        #pragma unroll
        for (int b = 0; b < 16; b++) {
            aA[b] += sA[b * 128 + j] * wa;
            aB[b] += sB[b * 128 + j] * wb;
        }
    }
    float bA = ba3[n], bB = bb3[n];
    #pragma unroll
    for (int b = 0; b < 16; b++) {
        float alpha = 1.f + softplus_f(aA[b] + bA);
        float beta  = 1.f + softplus_f(aB[b] + bB);
        float ab    = alpha + beta;
        float action = alpha / ab;
        float logB = lgammaf(alpha) + lgammaf(beta) - lgammaf(ab);
        float logp = (alpha - 1.f) * logf(action) + (beta - 1.f) * log1pf(-action) - logB;
        float ent  = logB - (alpha - 1.f) * psi_f(alpha) - (beta - 1.f) * psi_f(beta)
                   + (ab - 2.f) * psi_f(ab);
        out[b * N_NODES + n]           = action;
        out[80000 + b * N_NODES + n]   = logp;
        out[160000 + b * N_NODES + n]  = ent;
    }
}

// =================== launch ===================
extern "C" void kernel_launch(void* const* d_in, const int* in_sizes, int n_in,
                              void* d_out, int out_size) {
    const float* x   = (const float*)d_in[0];
    const int*   ei  = (const int*)  d_in[1];
    const float* W1  = (const float*)d_in[2];
    const float* b1  = (const float*)d_in[3];
    const float* W2  = (const float*)d_in[4];
    const float* b2  = (const float*)d_in[5];
    const float* Wc1 = (const float*)d_in[6];
    const float* bc1 = (const float*)d_in[7];
    const float* Wc2 = (const float*)d_in[8];
    const float* bc2 = (const float*)d_in[9];
    const float* Wc3 = (const float*)d_in[10];
    const float* bc3 = (const float*)d_in[11];
    const float* Wa1 = (const float*)d_in[12];
    const float* ba1 = (const float*)d_in[13];
    const float* Wa2 = (const float*)d_in[14];
    const float* ba2 = (const float*)d_in[15];
    const float* Wa3 = (const float*)d_in[16];
    const float* ba3 = (const float*)d_in[17];
    const float* Wb1 = (const float*)d_in[18];
    const float* bb1 = (const float*)d_in[19];
    const float* Wb2 = (const float*)d_in[20];
    const float* bb2 = (const float*)d_in[21];
    const float* Wb3 = (const float*)d_in[22];
    const float* bb3 = (const float*)d_in[23];
    float* out = (float*)d_out;

    const int E = in_sizes[1] / 2;   // 80000

    k_init<<<(N_NODES + 255) / 256, 256>>>();
    k_deg<<<(E + 255) / 256, 256>>>(ei, E);
    k_dinv<<<(N_NODES + 255) / 256, 256>>>();
    k_scan<<<1, 1024>>>(E + N_NODES);
    k_fill<<<(E + N_NODES + 255) / 256, 256>>>(ei, E);
    k_sortrows<<<(N_NODES + 127) / 128, 128>>>();
    k_xt<<<N_NODES, 512>>>(x);
    k_gcn1<<<N_NODES, 512>>>(W1, b1);
    k_gcn2<<<N_NODES, 512>>>(W2, b2);
    k_big<<<300, 128>>>(Wc1, Wa1, Wb1);
    k_reduce<<<(5120 + 127) / 128, 128>>>(bc1, ba1, bb1);
    k_mid<<<3, 128>>>(Wc2, bc2, Wc3, bc3, Wa2, ba2, Wb2, bb2, out);
    k_final<<<(N_NODES + 127) / 128, 128>>>(Wa3, ba3, Wb3, bb3, out);
}

// round 4
// speedup vs baseline: 1.1258x; 1.1258x over previous
#include <cuda_runtime.h>
#include <math.h>
#include <stdint.h>

#define N_NODES 5000
#define B_SZ    16
#define F_INDIM 32
#define D_DIM   64
#define E_EDGES 80000
#define NNZ     (E_EDGES + N_NODES)
#define K_OBS   (N_NODES * D_DIM)          // 320000
#define NBLK_C  125
#define NBLK_A  250
#define NBLK_B  250
#define NBLK_BIG (NBLK_C + NBLK_A + NBLK_B)   // 625

// ----- scratch (device globals; no allocation allowed) -----
__device__ int   g_deg[N_NODES];
__device__ float g_dinv[N_NODES];
__device__ int   g_off[N_NODES + 1];
__device__ int   g_cur[N_NODES];
__device__ int   g_esrc[NNZ];
__device__ int   g_eid[NNZ];
__device__ float g_ew[NNZ];
__device__ float g_XT[N_NODES * F_INDIM * B_SZ];     // [n][f][b]
__device__ float g_H1[N_NODES * D_DIM * B_SZ];       // [n][d][b]
__device__ float g_OBS[N_NODES * D_DIM * B_SZ];      // [k][b], k = n*64+d
__device__ float g_part[NBLK_BIG * 2048];            // per-block GEMM partials
__device__ float g_h1act[16 * 320];                  // tanh(layer1): C(1024) A(2048) B(2048)
__device__ float g_ha2[16 * 128];
__device__ float g_hb2[16 * 128];

// =================== graph preprocessing ===================

// transpose x [B,N,32] -> XT [n][f][b]; also init deg/cur (launch #0)
__global__ void k_xt(const float* __restrict__ x) {
    __shared__ float s[F_INDIM * 17];
    int n = blockIdx.x, t = threadIdx.x;       // 512 threads
    if (t == 0) { g_deg[n] = 1; g_cur[n] = 0; }   // self-loop counted
    int b = t >> 5, f = t & 31;
    s[f * 17 + b] = x[(b * N_NODES + n) * F_INDIM + f];
    __syncthreads();
    g_XT[n * 512 + t] = s[(t >> 4) * 17 + (t & 15)];
}

__global__ void k_deg(const int* __restrict__ ei, int E) {
    int e = blockIdx.x * blockDim.x + threadIdx.x;
    if (e < E) atomicAdd(&g_deg[ei[E + e]], 1);        // dst = ei[1][e]
}

// dinv + exclusive prefix sum of g_deg -> g_off (single block, 1024 threads)
__global__ void k_scan(int total) {
    __shared__ int s[1024];
    __shared__ int carry;
    int tid = threadIdx.x;
    for (int i = tid; i < N_NODES; i += 1024) g_dinv[i] = rsqrtf((float)g_deg[i]);
    if (tid == 0) carry = 0;
    __syncthreads();
    for (int base = 0; base < N_NODES; base += 1024) {
        int idx = base + tid;
        int v = (idx < N_NODES) ? g_deg[idx] : 0;
        s[tid] = v;
        __syncthreads();
        for (int o = 1; o < 1024; o <<= 1) {
            int t = (tid >= o) ? s[tid - o] : 0;
            __syncthreads();
            s[tid] += t;
            __syncthreads();
        }
        if (idx < N_NODES) g_off[idx] = carry + s[tid] - v;
        __syncthreads();
        if (tid == 0) carry += s[1023];
        __syncthreads();
    }
    if (tid == 0) g_off[N_NODES] = total;
}

__global__ void k_fill(const int* __restrict__ ei, int E) {
    int e = blockIdx.x * blockDim.x + threadIdx.x;
    if (e < E) {
        int s = ei[e], d = ei[E + e];
        int pos = g_off[d] + atomicAdd(&g_cur[d], 1);
        g_esrc[pos] = s;
        g_eid[pos]  = e;
        g_ew[pos] = g_dinv[s] * g_dinv[d];
    } else if (e < E + N_NODES) {
        int n = e - E;
        int pos = g_off[n] + atomicAdd(&g_cur[n], 1);
        g_esrc[pos] = n;
        g_eid[pos]  = e;
        g_ew[pos] = g_dinv[n] * g_dinv[n];
    }
}

// deterministic edge order within each row (insertion sort by original edge id)
__global__ void k_sortrows() {
    int n = blockIdx.x * blockDim.x + threadIdx.x;
    if (n >= N_NODES) return;
    int beg = g_off[n], end = g_off[n + 1];
    for (int i = beg + 1; i < end; i++) {
        int   id = g_eid[i], sr = g_esrc[i];
        float w  = g_ew[i];
        int j = i - 1;
        while (j >= beg && g_eid[j] > id) {
            g_eid[j + 1]  = g_eid[j];
            g_esrc[j + 1] = g_esrc[j];
            g_ew[j + 1]   = g_ew[j];
            j--;
        }
        g_eid[j + 1] = id; g_esrc[j + 1] = sr; g_ew[j + 1] = w;
    }
}

// =================== GCN layer 1 (agg in 32-dim, then W1, tanh) ===================
__global__ void k_gcn1(const float* __restrict__ W1, const float* __restrict__ b1) {
    __shared__ float sW[F_INDIM * D_DIM];   // 2048
    __shared__ float sAgg[512];
    __shared__ int   sSrc[128];
    __shared__ float sWt[128];
    int n = blockIdx.x, tid = threadIdx.x;  // 512 threads
    for (int i = tid; i < 2048; i += 512) sW[i] = W1[i];

    int beg = g_off[n], end = g_off[n + 1];
    float a0 = 0.f, a1 = 0.f, a2 = 0.f, a3 = 0.f;
    for (int p = beg; p < end;) {
        int cnt = min(128, end - p);
        if (tid < cnt) { sSrc[tid] = g_esrc[p + tid]; sWt[tid] = g_ew[p + tid]; }
        __syncthreads();
        int i = 0;
        for (; i + 4 <= cnt; i += 4) {
            a0 += sWt[i]     * g_XT[sSrc[i]     * 512 + tid];
            a1 += sWt[i + 1] * g_XT[sSrc[i + 1] * 512 + tid];
            a2 += sWt[i + 2] * g_XT[sSrc[i + 2] * 512 + tid];
            a3 += sWt[i + 3] * g_XT[sSrc[i + 3] * 512 + tid];
        }
        for (; i < cnt; i++) a0 += sWt[i] * g_XT[sSrc[i] * 512 + tid];
        p += cnt;
        __syncthreads();
    }
    sAgg[tid] = (a0 + a1) + (a2 + a3);
    __syncthreads();

    int b = tid & 15, d = tid >> 4;          // d in 0..31, also d+32
    float h0 = b1[d], h1 = b1[d + 32];
    #pragma unroll
    for (int f = 0; f < F_INDIM; f++) {
        float xa = sAgg[f * 16 + b];
        h0 += xa * sW[f * 64 + d];
        h1 += xa * sW[f * 64 + d + 32];
    }
    g_H1[(n * 64 + d) * 16 + b]        = tanhf(h0);
    g_H1[(n * 64 + d + 32) * 16 + b]   = tanhf(h1);
}

// =================== GCN layer 2 (agg in 64-dim, then W2, tanh -> OBS^T) ===================
__global__ void k_gcn2(const float* __restrict__ W2, const float* __restrict__ b2) {
    __shared__ float sW[D_DIM * D_DIM];     // 4096 = 16KB
    __shared__ float sAgg[1024];
    __shared__ int   sSrc[128];
    __shared__ float sWt[128];
    int n = blockIdx.x, tid = threadIdx.x;  // 512 threads
    for (int i = tid; i < 4096; i += 512) sW[i] = W2[i];

    int beg = g_off[n], end = g_off[n + 1];
    float lo0 = 0.f, lo1 = 0.f, lo2 = 0.f, lo3 = 0.f;
    float hi0 = 0.f, hi1 = 0.f, hi2 = 0.f, hi3 = 0.f;
    for (int p = beg; p < end;) {
        int cnt = min(128, end - p);
        if (tid < cnt) { sSrc[tid] = g_esrc[p + tid]; sWt[tid] = g_ew[p + tid]; }
        __syncthreads();
        int i = 0;
        for (; i + 4 <= cnt; i += 4) {
            int s0 = sSrc[i] * 1024, s1 = sSrc[i + 1] * 1024;
            int s2 = sSrc[i + 2] * 1024, s3 = sSrc[i + 3] * 1024;
            float w0 = sWt[i], w1 = sWt[i + 1], w2 = sWt[i + 2], w3 = sWt[i + 3];
            lo0 += w0 * g_H1[s0 + tid];
            lo1 += w1 * g_H1[s1 + tid];
            lo2 += w2 * g_H1[s2 + tid];
            lo3 += w3 * g_H1[s3 + tid];
            hi0 += w0 * g_H1[s0 + 512 + tid];
            hi1 += w1 * g_H1[s1 + 512 + tid];
            hi2 += w2 * g_H1[s2 + 512 + tid];
            hi3 += w3 * g_H1[s3 + 512 + tid];
        }
        for (; i < cnt; i++) {
            int s0 = sSrc[i] * 1024; float w0 = sWt[i];
            lo0 += w0 * g_H1[s0 + tid];
            hi0 += w0 * g_H1[s0 + 512 + tid];
        }
        p += cnt;
        __syncthreads();
    }
    sAgg[tid]       = (lo0 + lo1) + (lo2 + lo3);
    sAgg[tid + 512] = (hi0 + hi1) + (hi2 + hi3);
    __syncthreads();

    int b = tid & 15, d = tid >> 4;          // d in 0..31, also d+32
    float h0 = b2[d], h1 = b2[d + 32];
    #pragma unroll
    for (int dd = 0; dd < D_DIM; dd++) {
        float xa = sAgg[dd * 16 + b];
        h0 += xa * sW[dd * 64 + d];
        h1 += xa * sW[dd * 64 + d + 32];
    }
    g_OBS[(n * 64 + d) * 16 + b]      = tanhf(h0);
    g_OBS[(n * 64 + d + 32) * 16 + b] = tanhf(h1);
}

// =================== big GEMM: obs^T[320000][16] x {Wc1,Wa1,Wb1} ===================
// grid = 625, 256 threads: [0,125)=Wc1(64 cols, 2560 rows/blk),
// [125,375)=Wa1, [375,625)=Wb1 (128 cols, 1280 rows/blk)
__global__ void __launch_bounds__(256, 2) k_big(const float* __restrict__ Wc,
                                                const float* __restrict__ Wa,
                                                const float* __restrict__ Wb) {
    __shared__ float sObs[128 * 32];                  // 16KB (first 8KB = obs tile stage)
    unsigned long long* sObs64 = (unsigned long long*)sObs;

    int blk = blockIdx.x;
    const float* W; int ncols, segBlk, rows;
    if (blk < NBLK_C)               { W = Wc; ncols = 64;  segBlk = blk;            rows = 2560; }
    else if (blk < NBLK_C + NBLK_A) { W = Wa; ncols = 128; segBlk = blk - NBLK_C;   rows = 1280; }
    else                            { W = Wb; ncols = 128; segBlk = blk - (NBLK_C + NBLK_A); rows = 1280; }
    int k0 = segBlk * rows;

    const int tpr = ncols >> 2;        // threads covering one row: 16 or 32
    const int rpw = 32 / tpr;          // rows per warp step: 2 or 1
    int tid = threadIdx.x;
    int lane = tid & 31, w = tid >> 5; // 8 warps
    int slot = lane % tpr;             // column group (4 cols)
    int rr   = lane / tpr;

    unsigned long long acc[32];        // [c(4)][bpair(8)] f32x2
    #pragma unroll
    for (int i = 0; i < 32; i++) acc[i] = 0ULL;

    const int iters = 128 / (8 * rpw);  // 16 (128 cols) or 8 (64 cols)
    for (int kt = k0; kt < k0 + rows; kt += 128) {
        const float4* src = (const float4*)(g_OBS + (size_t)kt * 16);
        float4* dst4 = (float4*)sObs;
        dst4[tid]       = src[tid];
        dst4[tid + 256] = src[tid + 256];
        __syncthreads();

        for (int itg = 0; itg < iters; itg += 4) {
            // batch 4 independent weight loads (MLP=4)
            int r0 = ((itg + 0) * 8 + w) * rpw + rr;
            int r1 = ((itg + 1) * 8 + w) * rpw + rr;
            int r2 = ((itg + 2) * 8 + w) * rpw + rr;
            int r3 = ((itg + 3) * 8 + w) * rpw + rr;
            float4 w40 = *(const float4*)(W + (size_t)(kt + r0) * ncols + slot * 4);
            float4 w41 = *(const float4*)(W + (size_t)(kt + r1) * ncols + slot * 4);
            float4 w42 = *(const float4*)(W + (size_t)(kt + r2) * ncols + slot * 4);
            float4 w43 = *(const float4*)(W + (size_t)(kt + r3) * ncols + slot * 4);
            float4 wv[4] = {w40, w41, w42, w43};
            int    rv[4] = {r0, r1, r2, r3};
            #pragma unroll
            for (int u = 0; u < 4; u++) {
                unsigned long long wp0, wp1, wp2, wp3;
                asm("mov.b64 %0,{%1,%2};" : "=l"(wp0) : "f"(wv[u].x), "f"(wv[u].x));
                asm("mov.b64 %0,{%1,%2};" : "=l"(wp1) : "f"(wv[u].y), "f"(wv[u].y));
                asm("mov.b64 %0,{%1,%2};" : "=l"(wp2) : "f"(wv[u].z), "f"(wv[u].z));
                asm("mov.b64 %0,{%1,%2};" : "=l"(wp3) : "f"(wv[u].w), "f"(wv[u].w));
                const ulonglong2* ob2 = (const ulonglong2*)(sObs64 + rv[u] * 8);
                #pragma unroll
                for (int q = 0; q < 4; q++) {
                    ulonglong2 opair = ob2[q];
                    asm("fma.rn.f32x2 %0,%1,%2,%0;" : "+l"(acc[2*q])        : "l"(wp0), "l"(opair.x));
                    asm("fma.rn.f32x2 %0,%1,%2,%0;" : "+l"(acc[8 + 2*q])   : "l"(wp1), "l"(opair.x));
                    asm("fma.rn.f32x2 %0,%1,%2,%0;" : "+l"(acc[16 + 2*q])  : "l"(wp2), "l"(opair.x));
                    asm("fma.rn.f32x2 %0,%1,%2,%0;" : "+l"(acc[24 + 2*q])  : "l"(wp3), "l"(opair.x));
                    asm("fma.rn.f32x2 %0,%1,%2,%0;" : "+l"(acc[2*q+1])     : "l"(wp0), "l"(opair.y));
                    asm("fma.rn.f32x2 %0,%1,%2,%0;" : "+l"(acc[8 + 2*q+1]) : "l"(wp1), "l"(opair.y));
                    asm("fma.rn.f32x2 %0,%1,%2,%0;" : "+l"(acc[16 + 2*q+1]): "l"(wp2), "l"(opair.y));
                    asm("fma.rn.f32x2 %0,%1,%2,%0;" : "+l"(acc[24 + 2*q+1]): "l"(wp3), "l"(opair.y));
                }
            }
        }
        __syncthreads();
    }

    // epilogue: reduce 8 warps x rpw row-groups -> g_part[blk]
    for (int c = 0; c < 4; c++) {
        __syncthreads();
        #pragma unroll
        for (int p = 0; p < 8; p++) sObs64[tid * 8 + p] = acc[c * 8 + p];
        __syncthreads();
        for (int rid = tid; rid < tpr * 16; rid += 256) {
            int cslot = rid % tpr;
            int b = rid / tpr;
            float s = 0.f;
            for (int ww = 0; ww < 8; ww++)
                for (int r2 = 0; r2 < rpw; r2++)
                    s += sObs[(ww * 32 + r2 * tpr + cslot) * 16 + b];
            g_part[blk * 2048 + b * ncols + cslot * 4 + c] = s;
        }
    }
}

// reduce partials + bias + tanh -> g_h1act (5120 values)
__global__ void k_reduce(const float* __restrict__ bc1, const float* __restrict__ ba1,
                         const float* __restrict__ bb1) {
    int i = blockIdx.x * blockDim.x + threadIdx.x;
    if (i >= 5120) return;
    int blkBase, nblk, idx; float bias;
    if (i < 1024)      { blkBase = 0;               nblk = NBLK_C; idx = i;        bias = bc1[i & 63]; }
    else if (i < 3072) { blkBase = NBLK_C;          nblk = NBLK_A; idx = i - 1024; bias = ba1[(i - 1024) & 127]; }
    else               { blkBase = NBLK_C + NBLK_A; nblk = NBLK_B; idx = i - 3072; bias = bb1[(i - 3072) & 127]; }
    float s = bias;
    for (int q = 0; q < nblk; q++) s += g_part[(blkBase + q) * 2048 + idx];
    g_h1act[i] = tanhf(s);
}

// small middle MLP layers: block0 critic (-> out[240000..]), block1 alpha, block2 beta
__global__ void k_mid(const float* __restrict__ Wc2, const float* __restrict__ bc2,
                      const float* __restrict__ Wc3, const float* __restrict__ bc3,
                      const float* __restrict__ Wa2, const float* __restrict__ ba2,
                      const float* __restrict__ Wb2, const float* __restrict__ bb2,
                      float* __restrict__ out) {
    __shared__ float sH[2048];
    __shared__ float sH2[1024];
    int tid = threadIdx.x;               // 128 threads
    if (blockIdx.x == 0) {
        for (int i = tid; i < 1024; i += 128) sH[i] = g_h1act[i];
        __syncthreads();
        if (tid < 64) {
            int j = tid;
            float acc[16];
            #pragma unroll
            for (int b = 0; b < 16; b++) acc[b] = bc2[j];
            for (int k = 0; k < 64; k++) {
                float wv = Wc2[k * 64 + j];
                #pragma unroll
                for (int b = 0; b < 16; b++) acc[b] += sH[b * 64 + k] * wv;
            }
            #pragma unroll
            for (int b = 0; b < 16; b++) sH2[b * 64 + j] = tanhf(acc[b]);
        }
        __syncthreads();
        if (tid < 16) {
            float v = bc3[0];
            for (int j = 0; j < 64; j++) v += sH2[tid * 64 + j] * Wc3[j];
            out[240000 + tid] = v;
        }
    } else {
        const float* h1  = g_h1act + (blockIdx.x == 1 ? 1024 : 3072);
        const float* W2m = (blockIdx.x == 1 ? Wa2 : Wb2);
        const float* b2m = (blockIdx.x == 1 ? ba2 : bb2);
        float* dst       = (blockIdx.x == 1 ? g_ha2 : g_hb2);
        for (int i = tid; i < 2048; i += 128) sH[i] = h1[i];
        __syncthreads();
        int j = tid;                      // 128 threads = 128 cols
        float acc[16];
        #pragma unroll
        for (int b = 0; b < 16; b++) acc[b] = b2m[j];
        for (int k = 0; k < 128; k++) {
            float wv = W2m[k * 128 + j];
            #pragma unroll
            for (int b = 0; b < 16; b++) acc[b] += sH[b * 128 + k] * wv;
        }
        #pragma unroll
        for (int b = 0; b < 16; b++) dst[b * 128 + j] = tanhf(acc[b]);
    }
}

// =================== heads + Beta distribution ===================
__device__ __forceinline__ float softplus_f(float z) {
    return fmaxf(z, 0.f) + log1pf(expf(-fabsf(z)));
}
__device__ __forceinline__ float psi_f(float x) {
    // digamma for x >= 1 (alpha,beta >= 1): shift to >= 6, asymptotic series
    float r = 0.f;
    while (x < 6.f) { r -= 1.f / x; x += 1.f; }
    float xi = 1.f / x, xi2 = xi * xi;
    return r + logf(x) - 0.5f * xi
         - xi2 * (0.08333333333f - xi2 * (0.008333333333f - xi2 * 0.003968253968f));
}

__global__ void __launch_bounds__(128) k_final(const float* __restrict__ Wa3, const float* __restrict__ ba3,
                                               const float* __restrict__ Wb3, const float* __restrict__ bb3,
                                               float* __restrict__ out) {
    __shared__ float sA[2048], sB[2048];
    int tid = threadIdx.x;
    for (int i = tid; i < 2048; i += 128) { sA[i] = g_ha2[i]; sB[i] = g_hb2[i]; }
    __syncthreads();
    int n = blockIdx.x * 128 + tid;
    if (n >= N_NODES) return;

    float aA[16], aB[16];
    #pragma unroll
    for (int b = 0; b < 16; b++) { aA[b] = 0.f; aB[b] = 0.f; }
    for (int j = 0; j < 128; j++) {
        float wa = Wa3[j * N_NODES + n];
        float wb = Wb3[j * N_NODES + n];
        #pragma unroll
        for (int b = 0; b < 16; b++) {
            aA[b] += sA[b * 128 + j] * wa;
            aB[b] += sB[b * 128 + j] * wb;
        }
    }
    float bA = ba3[n], bB = bb3[n];
    #pragma unroll
    for (int b = 0; b < 16; b++) {
        float alpha = 1.f + softplus_f(aA[b] + bA);
        float beta  = 1.f + softplus_f(aB[b] + bB);
        float ab    = alpha + beta;
        float action = alpha / ab;
        float logB = lgammaf(alpha) + lgammaf(beta) - lgammaf(ab);
        float logp = (alpha - 1.f) * logf(action) + (beta - 1.f) * log1pf(-action) - logB;
        float ent  = logB - (alpha - 1.f) * psi_f(alpha) - (beta - 1.f) * psi_f(beta)
                   + (ab - 2.f) * psi_f(ab);
        out[b * N_NODES + n]           = action;
        out[80000 + b * N_NODES + n]   = logp;
        out[160000 + b * N_NODES + n]  = ent;
    }
}

// =================== launch ===================
extern "C" void kernel_launch(void* const* d_in, const int* in_sizes, int n_in,
                              void* d_out, int out_size) {
    const float* x   = (const float*)d_in[0];
    const int*   ei  = (const int*)  d_in[1];
    const float* W1  = (const float*)d_in[2];
    const float* b1  = (const float*)d_in[3];
    const float* W2  = (const float*)d_in[4];
    const float* b2  = (const float*)d_in[5];
    const float* Wc1 = (const float*)d_in[6];
    const float* bc1 = (const float*)d_in[7];
    const float* Wc2 = (const float*)d_in[8];
    const float* bc2 = (const float*)d_in[9];
    const float* Wc3 = (const float*)d_in[10];
    const float* bc3 = (const float*)d_in[11];
    const float* Wa1 = (const float*)d_in[12];
    const float* ba1 = (const float*)d_in[13];
    const float* Wa2 = (const float*)d_in[14];
    const float* ba2 = (const float*)d_in[15];
    const float* Wa3 = (const float*)d_in[16];
    const float* ba3 = (const float*)d_in[17];
    const float* Wb1 = (const float*)d_in[18];
    const float* bb1 = (const float*)d_in[19];
    const float* Wb2 = (const float*)d_in[20];
    const float* bb2 = (const float*)d_in[21];
    const float* Wb3 = (const float*)d_in[22];
    const float* bb3 = (const float*)d_in[23];
    float* out = (float*)d_out;

    const int E = in_sizes[1] / 2;   // 80000

    // launch order arranged so ncu's fixed "-s 5 -c 1" captures k_gcn1
    k_xt<<<N_NODES, 512>>>(x);                                   // 0 (also inits deg/cur)
    k_deg<<<(E + 255) / 256, 256>>>(ei, E);                      // 1
    k_scan<<<1, 1024>>>(E + N_NODES);                            // 2 (also dinv)
    k_fill<<<(E + N_NODES + 255) / 256, 256>>>(ei, E);           // 3
    k_sortrows<<<(N_NODES + 127) / 128, 128>>>();                // 4
    k_gcn1<<<N_NODES, 512>>>(W1, b1);                            // 5  <- profiled
    k_gcn2<<<N_NODES, 512>>>(W2, b2);                            // 6
    k_big<<<NBLK_BIG, 256>>>(Wc1, Wa1, Wb1);                     // 7
    k_reduce<<<(5120 + 127) / 128, 128>>>(bc1, ba1, bb1);        // 8
    k_mid<<<3, 128>>>(Wc2, bc2, Wc3, bc3, Wa2, ba2, Wb2, bb2, out); // 9
    k_final<<<(N_NODES + 127) / 128, 128>>>(Wa3, ba3, Wb3, bb3, out); // 10
}

// round 6
// speedup vs baseline: 1.3407x; 1.1908x over previous
#include <cuda_runtime.h>
#include <math.h>
#include <stdint.h>

#define N_NODES 5000
#define B_SZ    16
#define F_INDIM 32
#define D_DIM   64
#define NNZ_MAX (80000 + N_NODES)
#define K_OBS   (N_NODES * D_DIM)          // 320000
#define NBLK_C  250
#define NBLK_A  500
#define NBLK_B  500
#define NBLK_BIG (NBLK_C + NBLK_A + NBLK_B)   // 1250

// ----- scratch (device globals; zero-init at load; k_clean restores zeros) -----
__device__ int   g_deg[N_NODES];          // counts real in-edges (from 0)
__device__ float g_dinv[N_NODES];
__device__ int   g_off[N_NODES + 1];
__device__ int   g_cur[N_NODES];
__device__ int   g_esrc[NNZ_MAX];
__device__ int   g_eid[NNZ_MAX];
__device__ float g_ew[NNZ_MAX];
__device__ float g_XT[N_NODES * F_INDIM * B_SZ];     // [n][f][b]
__device__ float g_H1[N_NODES * D_DIM * B_SZ];       // [n][d][b]
__device__ float g_OBS[N_NODES * D_DIM * B_SZ];      // [k][b], k = n*64+d
__device__ float g_part[NBLK_BIG * 2048];            // per-block GEMM partials
__device__ float g_h1act[16 * 320];                  // tanh(layer1): C(1024) A(2048) B(2048)
__device__ float g_ha2[16 * 128];
__device__ float g_hb2[16 * 128];

// =================== launch 0: transpose x + degree count ===================
__global__ void k_xtdeg(const float* __restrict__ x, const int* __restrict__ ei, int E) {
    __shared__ float s[F_INDIM * 17];
    int n = blockIdx.x, t = threadIdx.x;       // 512 threads
    // this block also counts 16 edges' degrees (E = 80000 = 5000*16)
    int epb = (E + N_NODES - 1) / N_NODES;
    if (t < epb) {
        int e = n * epb + t;
        if (e < E) atomicAdd(&g_deg[ei[E + e]], 1);
    }
    int b = t >> 5, f = t & 31;
    s[f * 17 + b] = x[(b * N_NODES + n) * F_INDIM + f];
    __syncthreads();
    g_XT[n * 512 + t] = s[(t >> 4) * 17 + (t & 15)];
}

// =================== launch 1: dinv + exclusive scan of (deg+1) ===================
__global__ void k_scan(int total) {
    __shared__ int warpsum[32];
    __shared__ int carry_s;
    int tid = threadIdx.x, lane = tid & 31, wid = tid >> 5;
    if (tid == 0) carry_s = 0;
    __syncthreads();
    for (int base = 0; base < N_NODES; base += 1024) {
        int idx = base + tid;
        int v = 0;
        if (idx < N_NODES) {
            int d = g_deg[idx] + 1;           // + self-loop
            v = d;
            g_dinv[idx] = rsqrtf((float)d);
        }
        int sc = v;
        #pragma unroll
        for (int o = 1; o < 32; o <<= 1) {
            int tpv = __shfl_up_sync(0xFFFFFFFFu, sc, o);
            if (lane >= o) sc += tpv;
        }
        if (lane == 31) warpsum[wid] = sc;
        __syncthreads();
        if (wid == 0) {
            int ws = warpsum[lane];
            #pragma unroll
            for (int o = 1; o < 32; o <<= 1) {
                int tpv = __shfl_up_sync(0xFFFFFFFFu, ws, o);
                if (lane >= o) ws += tpv;
            }
            warpsum[lane] = ws;
        }
        __syncthreads();
        int wpre = (wid == 0) ? 0 : warpsum[wid - 1];
        if (idx < N_NODES) g_off[idx] = carry_s + wpre + sc - v;
        __syncthreads();
        if (tid == 0) carry_s += warpsum[31];
        __syncthreads();
    }
    if (tid == 0) g_off[N_NODES] = total;
}

// =================== launch 2: CSR fill (slot order nondet; eid kept as sort key) ===================
__global__ void k_fill(const int* __restrict__ ei, int E) {
    int e = blockIdx.x * blockDim.x + threadIdx.x;
    if (e < E) {
        int s = ei[e], d = ei[E + e];
        int pos = g_off[d] + atomicAdd(&g_cur[d], 1);
        g_esrc[pos] = s;
        g_eid[pos]  = e;
        g_ew[pos]   = g_dinv[s] * g_dinv[d];
    } else if (e < E + N_NODES) {
        int n = e - E;
        int pos = g_off[n] + atomicAdd(&g_cur[n], 1);
        g_esrc[pos] = n;
        g_eid[pos]  = e;
        g_ew[pos]   = g_dinv[n] * g_dinv[n];
    }
}

// =================== launch 3 (PROFILED): GCN layer 1 ===================
__global__ void k_gcn1(const float* __restrict__ W1, const float* __restrict__ b1) {
    __shared__ float sW[F_INDIM * D_DIM];   // 8KB
    __shared__ float sAgg[512];
    __shared__ int   sS0[128]; __shared__ float sW0[128]; __shared__ int sE[128];
    __shared__ int   sSrc[128]; __shared__ float sWt[128];
    int n = blockIdx.x, tid = threadIdx.x;  // 512 threads
    for (int i = tid; i < 2048; i += 512) sW[i] = W1[i];

    int beg = g_off[n], end = g_off[n + 1];
    float a0 = 0.f, a1 = 0.f, a2 = 0.f, a3 = 0.f;
    for (int p = beg; p < end;) {
        int cnt = min(128, end - p);
        if (tid < cnt) { sS0[tid] = g_esrc[p + tid]; sW0[tid] = g_ew[p + tid]; sE[tid] = g_eid[p + tid]; }
        __syncthreads();
        if (tid < cnt) {   // deterministic rank-sort by edge id
            int my = sE[tid], rk = 0;
            for (int j = 0; j < cnt; j++) rk += (sE[j] < my);
            sSrc[rk] = sS0[tid]; sWt[rk] = sW0[tid];
        }
        __syncthreads();
        int i = 0;
        for (; i + 4 <= cnt; i += 4) {
            a0 += sWt[i]     * g_XT[sSrc[i]     * 512 + tid];
            a1 += sWt[i + 1] * g_XT[sSrc[i + 1] * 512 + tid];
            a2 += sWt[i + 2] * g_XT[sSrc[i + 2] * 512 + tid];
            a3 += sWt[i + 3] * g_XT[sSrc[i + 3] * 512 + tid];
        }
        for (; i < cnt; i++) a0 += sWt[i] * g_XT[sSrc[i] * 512 + tid];
        p += cnt;
        __syncthreads();
    }
    sAgg[tid] = (a0 + a1) + (a2 + a3);
    __syncthreads();

    int b = tid & 15, d = tid >> 4;          // d in 0..31, also d+32
    float h0 = b1[d], h1 = b1[d + 32];
    #pragma unroll
    for (int f = 0; f < F_INDIM; f++) {
        float xa = sAgg[f * 16 + b];
        h0 += xa * sW[f * 64 + d];
        h1 += xa * sW[f * 64 + d + 32];
    }
    g_H1[(n * 64 + d) * 16 + b]        = tanhf(h0);
    g_H1[(n * 64 + d + 32) * 16 + b]   = tanhf(h1);
}

// =================== launch 4: GCN layer 2 ===================
__global__ void k_gcn2(const float* __restrict__ W2, const float* __restrict__ b2) {
    __shared__ float sW[D_DIM * D_DIM];     // 16KB
    __shared__ float sAgg[1024];
    __shared__ int   sS0[128]; __shared__ float sW0[128]; __shared__ int sE[128];
    __shared__ int   sSrc[128]; __shared__ float sWt[128];
    int n = blockIdx.x, tid = threadIdx.x;  // 512 threads
    for (int i = tid; i < 4096; i += 512) sW[i] = W2[i];

    int beg = g_off[n], end = g_off[n + 1];
    float lo0 = 0.f, lo1 = 0.f, lo2 = 0.f, lo3 = 0.f;
    float hi0 = 0.f, hi1 = 0.f, hi2 = 0.f, hi3 = 0.f;
    for (int p = beg; p < end;) {
        int cnt = min(128, end - p);
        if (tid < cnt) { sS0[tid] = g_esrc[p + tid]; sW0[tid] = g_ew[p + tid]; sE[tid] = g_eid[p + tid]; }
        __syncthreads();
        if (tid < cnt) {
            int my = sE[tid], rk = 0;
            for (int j = 0; j < cnt; j++) rk += (sE[j] < my);
            sSrc[rk] = sS0[tid]; sWt[rk] = sW0[tid];
        }
        __syncthreads();
        int i = 0;
        for (; i + 4 <= cnt; i += 4) {
            int s0 = sSrc[i] * 1024, s1 = sSrc[i + 1] * 1024;
            int s2 = sSrc[i + 2] * 1024, s3 = sSrc[i + 3] * 1024;
            float w0 = sWt[i], w1 = sWt[i + 1], w2 = sWt[i + 2], w3 = sWt[i + 3];
            lo0 += w0 * g_H1[s0 + tid];
            lo1 += w1 * g_H1[s1 + tid];
            lo2 += w2 * g_H1[s2 + tid];
            lo3 += w3 * g_H1[s3 + tid];
            hi0 += w0 * g_H1[s0 + 512 + tid];
            hi1 += w1 * g_H1[s1 + 512 + tid];
            hi2 += w2 * g_H1[s2 + 512 + tid];
            hi3 += w3 * g_H1[s3 + 512 + tid];
        }
        for (; i < cnt; i++) {
            int s0 = sSrc[i] * 1024; float w0 = sWt[i];
            lo0 += w0 * g_H1[s0 + tid];
            hi0 += w0 * g_H1[s0 + 512 + tid];
        }
        p += cnt;
        __syncthreads();
    }
    sAgg[tid]       = (lo0 + lo1) + (lo2 + lo3);
    sAgg[tid + 512] = (hi0 + hi1) + (hi2 + hi3);
    __syncthreads();

    int b = tid & 15, d = tid >> 4;
    float h0 = b2[d], h1 = b2[d + 32];
    #pragma unroll
    for (int dd = 0; dd < D_DIM; dd++) {
        float xa = sAgg[dd * 16 + b];
        h0 += xa * sW[dd * 64 + d];
        h1 += xa * sW[dd * 64 + d + 32];
    }
    g_OBS[(n * 64 + d) * 16 + b]      = tanhf(h0);
    g_OBS[(n * 64 + d + 32) * 16 + b] = tanhf(h1);
}

// =================== launch 5: big GEMM (2 cols/thread, no spills) ===================
// grid = 1250: [0,250)=Wc1 (64 cols, 1280 rows/blk); [250,750)=Wa1; [750,1250)=Wb1 (128 cols, 640 rows/blk)
__global__ void __launch_bounds__(256, 3) k_big(const float* __restrict__ Wc,
                                                const float* __restrict__ Wa,
                                                const float* __restrict__ Wb) {
    __shared__ __align__(16) float sBuf[8192];        // 32KB: 8KB obs stage / 32KB epilogue
    unsigned long long* sBuf64 = (unsigned long long*)sBuf;

    int blk = blockIdx.x;
    const float* W; int ncols, segBlk, rows;
    if (blk < NBLK_C)               { W = Wc; ncols = 64;  segBlk = blk;            rows = 1280; }
    else if (blk < NBLK_C + NBLK_A) { W = Wa; ncols = 128; segBlk = blk - NBLK_C;   rows = 640; }
    else                            { W = Wb; ncols = 128; segBlk = blk - (NBLK_C + NBLK_A); rows = 640; }
    int k0 = segBlk * rows;

    const int tpr = ncols >> 1;        // threads per row: 32 or 64
    const int nrs = 256 / tpr;         // rows per step: 8 or 4
    int tid  = threadIdx.x;
    int slot = tid % tpr;              // column pair index (cols 2*slot, 2*slot+1)
    int roff = tid / tpr;

    unsigned long long acc[16];        // [col(2)][bpair(8)]
    #pragma unroll
    for (int i = 0; i < 16; i++) acc[i] = 0ULL;

    const int steps = 128 / nrs;       // 16 or 32
    for (int kt = k0; kt < k0 + rows; kt += 128) {
        const float4* src = (const float4*)(g_OBS + (size_t)kt * 16);
        float4* dst4 = (float4*)sBuf;
        dst4[tid]       = src[tid];
        dst4[tid + 256] = src[tid + 256];
        __syncthreads();

        for (int itg = 0; itg < steps; itg += 4) {
            float2 wv[4];
            #pragma unroll
            for (int u = 0; u < 4; u++) {
                int r = (itg + u) * nrs + roff;
                wv[u] = *(const float2*)(W + (size_t)(kt + r) * ncols + 2 * slot);
            }
            #pragma unroll
            for (int u = 0; u < 4; u++) {
                int r = (itg + u) * nrs + roff;
                unsigned long long wp0, wp1;
                asm("mov.b64 %0,{%1,%2};" : "=l"(wp0) : "f"(wv[u].x), "f"(wv[u].x));
                asm("mov.b64 %0,{%1,%2};" : "=l"(wp1) : "f"(wv[u].y), "f"(wv[u].y));
                const ulonglong2* ob2 = (const ulonglong2*)(sBuf64 + r * 8);
                #pragma unroll
                for (int q = 0; q < 4; q++) {
                    ulonglong2 op = ob2[q];   // broadcast across lanes (same r)
                    asm("fma.rn.f32x2 %0,%1,%2,%0;" : "+l"(acc[2*q])     : "l"(wp0), "l"(op.x));
                    asm("fma.rn.f32x2 %0,%1,%2,%0;" : "+l"(acc[2*q+1])   : "l"(wp0), "l"(op.y));
                    asm("fma.rn.f32x2 %0,%1,%2,%0;" : "+l"(acc[8+2*q])   : "l"(wp1), "l"(op.x));
                    asm("fma.rn.f32x2 %0,%1,%2,%0;" : "+l"(acc[8+2*q+1]) : "l"(wp1), "l"(op.y));
                }
            }
        }
        __syncthreads();
    }

    // epilogue: stage all accs (32KB), reduce over roff groups
    #pragma unroll
    for (int j = 0; j < 16; j++) sBuf64[tid * 16 + j] = acc[j];
    __syncthreads();
    for (int idx2 = tid; idx2 < tpr * 16; idx2 += 256) {
        int sIdx = idx2 >> 4, j = idx2 & 15;
        float lo = 0.f, hi = 0.f;
        for (int g = 0; g < nrs; g++) {
            int base = ((g * tpr + sIdx) * 16 + j) * 2;
            lo += sBuf[base];
            hi += sBuf[base + 1];
        }
        int col = 2 * sIdx + (j >> 3);
        int p = j & 7;
        g_part[blk * 2048 + (2 * p) * ncols + col]     = lo;
        g_part[blk * 2048 + (2 * p + 1) * ncols + col] = hi;
    }
}

// =================== launch 6: reduce partials (8-way split, coalesced) ===================
__global__ void k_reduce(const float* __restrict__ bc1, const float* __restrict__ ba1,
                         const float* __restrict__ bb1) {
    __shared__ float red[8][33];
    int tid = threadIdx.x;               // 256
    int o_local = tid & 31, t8 = tid >> 5;
    int o = blockIdx.x * 32 + o_local;   // 0..5119 (grid 160)
    int blkBase, nblk, idx; float bias;
    if (o < 1024)      { blkBase = 0;               nblk = NBLK_C; idx = o;        bias = bc1[idx & 63]; }
    else if (o < 3072) { blkBase = NBLK_C;          nblk = NBLK_A; idx = o - 1024; bias = ba1[idx & 127]; }
    else               { blkBase = NBLK_C + NBLK_A; nblk = NBLK_B; idx = o - 3072; bias = bb1[idx & 127]; }
    float s = 0.f;
    for (int q = t8; q < nblk; q += 8) s += g_part[(size_t)(blkBase + q) * 2048 + idx];
    red[t8][o_local] = s;
    __syncthreads();
    if (t8 == 0) {
        float tot = bias;
        #pragma unroll
        for (int g = 0; g < 8; g++) tot += red[g][o_local];
        g_h1act[o] = tanhf(tot);
    }
}

// =================== launch 7: middle MLP layers ===================
__global__ void k_mid(const float* __restrict__ Wc2, const float* __restrict__ bc2,
                      const float* __restrict__ Wc3, const float* __restrict__ bc3,
                      const float* __restrict__ Wa2, const float* __restrict__ ba2,
                      const float* __restrict__ Wb2, const float* __restrict__ bb2,
                      float* __restrict__ out) {
    __shared__ float sH[2048];
    __shared__ float sH2[1024];
    int tid = threadIdx.x;               // 128 threads
    if (blockIdx.x == 0) {
        for (int i = tid; i < 1024; i += 128) sH[i] = g_h1act[i];
        __syncthreads();
        if (tid < 64) {
            int j = tid;
            float acc[16];
            #pragma unroll
            for (int b = 0; b < 16; b++) acc[b] = bc2[j];
            for (int k = 0; k < 64; k++) {
                float wv = Wc2[k * 64 + j];
                #pragma unroll
                for (int b = 0; b < 16; b++) acc[b] += sH[b * 64 + k] * wv;
            }
            #pragma unroll
            for (int b = 0; b < 16; b++) sH2[b * 64 + j] = tanhf(acc[b]);
        }
        __syncthreads();
        if (tid < 16) {
            float v = bc3[0];
            for (int j = 0; j < 64; j++) v += sH2[tid * 64 + j] * Wc3[j];
            out[240000 + tid] = v;
        }
    } else {
        const float* h1  = g_h1act + (blockIdx.x == 1 ? 1024 : 3072);
        const float* W2m = (blockIdx.x == 1 ? Wa2 : Wb2);
        const float* b2m = (blockIdx.x == 1 ? ba2 : bb2);
        float* dst       = (blockIdx.x == 1 ? g_ha2 : g_hb2);
        for (int i = tid; i < 2048; i += 128) sH[i] = h1[i];
        __syncthreads();
        int j = tid;
        float acc[16];
        #pragma unroll
        for (int b = 0; b < 16; b++) acc[b] = b2m[j];
        for (int k = 0; k < 128; k++) {
            float wv = W2m[k * 128 + j];
            #pragma unroll
            for (int b = 0; b < 16; b++) acc[b] += sH[b * 128 + k] * wv;
        }
        #pragma unroll
        for (int b = 0; b < 16; b++) dst[b * 128 + j] = tanhf(acc[b]);
    }
}

// =================== launch 8: heads + Beta distribution ===================
__device__ __forceinline__ float softplus_f(float z) {
    return fmaxf(z, 0.f) + log1pf(expf(-fabsf(z)));
}
__device__ __forceinline__ float psi_f(float x) {
    float r = 0.f;
    while (x < 6.f) { r -= 1.f / x; x += 1.f; }
    float xi = 1.f / x, xi2 = xi * xi;
    return r + logf(x) - 0.5f * xi
         - xi2 * (0.08333333333f - xi2 * (0.008333333333f - xi2 * 0.003968253968f));
}

__global__ void __launch_bounds__(128) k_final(const float* __restrict__ Wa3, const float* __restrict__ ba3,
                                               const float* __restrict__ Wb3, const float* __restrict__ bb3,
                                               float* __restrict__ out) {
    __shared__ float sA[2048], sB[2048];
    int tid = threadIdx.x;
    for (int i = tid; i < 2048; i += 128) { sA[i] = g_ha2[i]; sB[i] = g_hb2[i]; }
    __syncthreads();
    int n = blockIdx.x * 128 + tid;
    if (n >= N_NODES) return;

    float aA[16], aB[16];
    #pragma unroll
    for (int b = 0; b < 16; b++) { aA[b] = 0.f; aB[b] = 0.f; }
    for (int j = 0; j < 128; j++) {
        float wa = Wa3[j * N_NODES + n];
        float wb = Wb3[j * N_NODES + n];
        #pragma unroll
        for (int b = 0; b < 16; b++) {
            aA[b] += sA[b * 128 + j] * wa;
            aB[b] += sB[b * 128 + j] * wb;
        }
    }
    float bA = ba3[n], bB = bb3[n];
    #pragma unroll
    for (int b = 0; b < 16; b++) {
        float alpha = 1.f + softplus_f(aA[b] + bA);
        float beta  = 1.f + softplus_f(aB[b] + bB);
        float ab    = alpha + beta;
        float action = alpha / ab;
        float logB = lgammaf(alpha) + lgammaf(beta) - lgammaf(ab);
        float logp = (alpha - 1.f) * logf(action) + (beta - 1.f) * log1pf(-action) - logB;
        float ent  = logB - (alpha - 1.f) * psi_f(alpha) - (beta - 1.f) * psi_f(beta)
                   + (ab - 2.f) * psi_f(ab);
        out[b * N_NODES + n]           = action;
        out[80000 + b * N_NODES + n]   = logp;
        out[160000 + b * N_NODES + n]  = ent;
    }
}

// =================== launch 9: reset state for next replay ===================
__global__ void k_clean() {
    int i = blockIdx.x * blockDim.x + threadIdx.x;
    if (i < N_NODES) { g_deg[i] = 0; g_cur[i] = 0; }
}

// =================== launch ===================
extern "C" void kernel_launch(void* const* d_in, const int* in_sizes, int n_in,
                              void* d_out, int out_size) {
    const float* x   = (const float*)d_in[0];
    const int*   ei  = (const int*)  d_in[1];
    const float* W1  = (const float*)d_in[2];
    const float* b1  = (const float*)d_in[3];
    const float* W2  = (const float*)d_in[4];
    const float* b2  = (const float*)d_in[5];
    const float* Wc1 = (const float*)d_in[6];
    const float* bc1 = (const float*)d_in[7];
    const float* Wc2 = (const float*)d_in[8];
    const float* bc2 = (const float*)d_in[9];
    const float* Wc3 = (const float*)d_in[10];
    const float* bc3 = (const float*)d_in[11];
    const float* Wa1 = (const float*)d_in[12];
    const float* ba1 = (const float*)d_in[13];
    const float* Wa2 = (const float*)d_in[14];
    const float* ba2 = (const float*)d_in[15];
    const float* Wa3 = (const float*)d_in[16];
    const float* ba3 = (const float*)d_in[17];
    const float* Wb1 = (const float*)d_in[18];
    const float* bb1 = (const float*)d_in[19];
    const float* Wb2 = (const float*)d_in[20];
    const float* bb2 = (const float*)d_in[21];
    const float* Wb3 = (const float*)d_in[22];
    const float* bb3 = (const float*)d_in[23];
    float* out = (float*)d_out;

    const int E = in_sizes[1] / 2;   // 80000

    k_xtdeg<<<N_NODES, 512>>>(x, ei, E);                              // 0
    k_scan<<<1, 1024>>>(E + N_NODES);                                 // 1
    k_fill<<<(E + N_NODES + 255) / 256, 256>>>(ei, E);                // 2
    k_gcn1<<<N_NODES, 512>>>(W1, b1);                                 // 3  <- profiled
    k_gcn2<<<N_NODES, 512>>>(W2, b2);                                 // 4
    k_big<<<NBLK_BIG, 256>>>(Wc1, Wa1, Wb1);                          // 5
    k_reduce<<<160, 256>>>(bc1, ba1, bb1);                            // 6
    k_mid<<<3, 128>>>(Wc2, bc2, Wc3, bc3, Wa2, ba2, Wb2, bb2, out);   // 7
    k_final<<<(N_NODES + 127) / 128, 128>>>(Wa3, ba3, Wb3, bb3, out); // 8
    k_clean<<<(N_NODES + 255) / 256, 256>>>();                        // 9
}

// round 7
// speedup vs baseline: 1.5925x; 1.1879x over previous
#include <cuda_runtime.h>
#include <math.h>
#include <stdint.h>

#define N_NODES 5000
#define B_SZ    16
#define F_INDIM 32
#define D_DIM   64
#define NNZ_MAX (80000 + N_NODES)
#define CH      64                          // max edges per row chunk (max in-deg ~45)
#define NBLK_C  250
#define NBLK_A  500
#define NBLK_B  500
#define NBLK_BIG (NBLK_C + NBLK_A + NBLK_B)   // 1250

// ----- scratch (device globals; zero-init at load; k_clean restores zeros) -----
__device__ int   g_deg[N_NODES];
__device__ float g_dinv[N_NODES];
__device__ int   g_off[N_NODES + 1];
__device__ int   g_cur[N_NODES];
__device__ int   g_esrc[NNZ_MAX];
__device__ int   g_eid[NNZ_MAX];
__device__ float g_ew[NNZ_MAX];
__device__ float g_XT[N_NODES * F_INDIM * B_SZ];     // [n][f][b]
__device__ float g_H1[N_NODES * D_DIM * B_SZ];       // [n][d][b]
__device__ float g_OBS[N_NODES * D_DIM * B_SZ];      // [k][b], k = n*64+d
__device__ float g_part[NBLK_BIG * 2048];
__device__ float g_h1act[16 * 320];                  // C(1024) A(2048) B(2048)
__device__ float g_ha2[16 * 128];
__device__ float g_hb2[16 * 128];

__device__ __forceinline__ void bar_grp(int id) {
    asm volatile("bar.sync %0, 128;" :: "r"(id) : "memory");
}

// =================== launch 0: transpose x + degree count ===================
__global__ void k_xtdeg(const float* __restrict__ x, const int* __restrict__ ei, int E) {
    __shared__ float s[F_INDIM * 17];
    int n = blockIdx.x, t = threadIdx.x;       // 512 threads
    int epb = (E + N_NODES - 1) / N_NODES;     // 16
    if (t < epb) {
        int e = n * epb + t;
        if (e < E) atomicAdd(&g_deg[ei[E + e]], 1);
    }
    int b = t >> 5, f = t & 31;
    s[f * 17 + b] = x[(b * N_NODES + n) * F_INDIM + f];
    __syncthreads();
    g_XT[n * 512 + t] = s[(t >> 4) * 17 + (t & 15)];
}

// =================== launch 1: dinv + exclusive scan of (deg+1) ===================
__global__ void k_scan(int total) {
    __shared__ int warpsum[32];
    __shared__ int carry_s;
    int tid = threadIdx.x, lane = tid & 31, wid = tid >> 5;
    if (tid == 0) carry_s = 0;
    __syncthreads();
    for (int base = 0; base < N_NODES; base += 1024) {
        int idx = base + tid;
        int v = 0;
        if (idx < N_NODES) {
            int d = g_deg[idx] + 1;           // + self-loop
            v = d;
            g_dinv[idx] = rsqrtf((float)d);
        }
        int sc = v;
        #pragma unroll
        for (int o = 1; o < 32; o <<= 1) {
            int tpv = __shfl_up_sync(0xFFFFFFFFu, sc, o);
            if (lane >= o) sc += tpv;
        }
        if (lane == 31) warpsum[wid] = sc;
        __syncthreads();
        if (wid == 0) {
            int ws = warpsum[lane];
            #pragma unroll
            for (int o = 1; o < 32; o <<= 1) {
                int tpv = __shfl_up_sync(0xFFFFFFFFu, ws, o);
                if (lane >= o) ws += tpv;
            }
            warpsum[lane] = ws;
        }
        __syncthreads();
        int wpre = (wid == 0) ? 0 : warpsum[wid - 1];
        if (idx < N_NODES) g_off[idx] = carry_s + wpre + sc - v;
        __syncthreads();
        if (tid == 0) carry_s += warpsum[31];
        __syncthreads();
    }
    if (tid == 0) g_off[N_NODES] = total;
}

// =================== launch 2: CSR fill ===================
__global__ void k_fill(const int* __restrict__ ei, int E) {
    int e = blockIdx.x * blockDim.x + threadIdx.x;
    if (e < E) {
        int s = ei[e], d = ei[E + e];
        int pos = g_off[d] + atomicAdd(&g_cur[d], 1);
        g_esrc[pos] = s;
        g_eid[pos]  = e;
        g_ew[pos]   = g_dinv[s] * g_dinv[d];
    } else if (e < E + N_NODES) {
        int n = e - E;
        int pos = g_off[n] + atomicAdd(&g_cur[n], 1);
        g_esrc[pos] = n;
        g_eid[pos]  = e;
        g_ew[pos]   = g_dinv[n] * g_dinv[n];
    }
}

// =================== launch 3 (PROFILED): GCN layer 1 ===================
// 4 nodes/block, 128 threads/node-group; float4 gathers; w-shared epilogue.
__global__ void __launch_bounds__(512) k_gcn1(const float* __restrict__ W1, const float* __restrict__ b1) {
    __shared__ float sW[F_INDIM * D_DIM];      // 8KB
    __shared__ float sAgg[4 * 512];            // 8KB
    __shared__ int   sS0[4][CH]; __shared__ float sW0[4][CH]; __shared__ int sE[4][CH];
    __shared__ int   sSrc[4][CH]; __shared__ float sWt[4][CH];
    int tid = threadIdx.x;
    int g = tid >> 7, wt = tid & 127;
    int n = blockIdx.x * 4 + g;
    for (int i = tid; i < 2048; i += 512) sW[i] = W1[i];

    int beg = g_off[n], end = g_off[n + 1];
    float4 acc = make_float4(0.f, 0.f, 0.f, 0.f);
    for (int p = beg; p < end; p += CH) {
        int cnt = min(CH, end - p);
        if (wt < cnt) { sS0[g][wt] = g_esrc[p + wt]; sW0[g][wt] = g_ew[p + wt]; sE[g][wt] = g_eid[p + wt]; }
        bar_grp(g + 1);
        if (wt < cnt) {   // deterministic rank-sort by edge id
            int my = sE[g][wt], rk = 0;
            for (int j = 0; j < cnt; j++) rk += (sE[g][j] < my);
            sSrc[g][rk] = sS0[g][wt]; sWt[g][rk] = sW0[g][wt];
        }
        bar_grp(g + 1);
        int i = 0;
        for (; i + 4 <= cnt; i += 4) {
            float w0 = sWt[g][i], w1 = sWt[g][i + 1], w2 = sWt[g][i + 2], w3 = sWt[g][i + 3];
            float4 x0 = *(const float4*)&g_XT[sSrc[g][i]     * 512 + wt * 4];
            float4 x1 = *(const float4*)&g_XT[sSrc[g][i + 1] * 512 + wt * 4];
            float4 x2 = *(const float4*)&g_XT[sSrc[g][i + 2] * 512 + wt * 4];
            float4 x3 = *(const float4*)&g_XT[sSrc[g][i + 3] * 512 + wt * 4];
            acc.x += w0 * x0.x + w1 * x1.x + w2 * x2.x + w3 * x3.x;
            acc.y += w0 * x0.y + w1 * x1.y + w2 * x2.y + w3 * x3.y;
            acc.z += w0 * x0.z + w1 * x1.z + w2 * x2.z + w3 * x3.z;
            acc.w += w0 * x0.w + w1 * x1.w + w2 * x2.w + w3 * x3.w;
        }
        for (; i < cnt; i++) {
            float w0 = sWt[g][i];
            float4 x0 = *(const float4*)&g_XT[sSrc[g][i] * 512 + wt * 4];
            acc.x += w0 * x0.x; acc.y += w0 * x0.y; acc.z += w0 * x0.z; acc.w += w0 * x0.w;
        }
        bar_grp(g + 1);
    }
    *(float4*)&sAgg[g * 512 + wt * 4] = acc;
    __syncthreads();

    // epilogue: 4 nodes, weights shared across nodes
    int b = tid & 15, d = tid >> 4;            // d in 0..31 (also d+32)
    float h[8];
    float bi0 = b1[d], bi1 = b1[d + 32];
    #pragma unroll
    for (int gg = 0; gg < 4; gg++) { h[2 * gg] = bi0; h[2 * gg + 1] = bi1; }
    #pragma unroll 4
    for (int f = 0; f < F_INDIM; f++) {
        float w0 = sW[f * 64 + d], w1 = sW[f * 64 + d + 32];
        #pragma unroll
        for (int gg = 0; gg < 4; gg++) {
            float xa = sAgg[gg * 512 + f * 16 + b];
            h[2 * gg]     += xa * w0;
            h[2 * gg + 1] += xa * w1;
        }
    }
    int n0 = blockIdx.x * 4;
    #pragma unroll
    for (int gg = 0; gg < 4; gg++) {
        g_H1[((n0 + gg) * 64 + d) * 16 + b]      = tanhf(h[2 * gg]);
        g_H1[((n0 + gg) * 64 + d + 32) * 16 + b] = tanhf(h[2 * gg + 1]);
    }
}

// =================== launch 4: GCN layer 2 ===================
__global__ void __launch_bounds__(512) k_gcn2(const float* __restrict__ W2, const float* __restrict__ b2) {
    __shared__ float sW[D_DIM * D_DIM];        // 16KB
    __shared__ float sAgg[4 * 1024];           // 16KB
    __shared__ int   sS0[4][CH]; __shared__ float sW0[4][CH]; __shared__ int sE[4][CH];
    __shared__ int   sSrc[4][CH]; __shared__ float sWt[4][CH];
    int tid = threadIdx.x;
    int g = tid >> 7, wt = tid & 127;
    int n = blockIdx.x * 4 + g;
    for (int i = tid; i < 4096; i += 512) sW[i] = W2[i];

    int beg = g_off[n], end = g_off[n + 1];
    float4 aLo = make_float4(0.f, 0.f, 0.f, 0.f);
    float4 aHi = make_float4(0.f, 0.f, 0.f, 0.f);
    for (int p = beg; p < end; p += CH) {
        int cnt = min(CH, end - p);
        if (wt < cnt) { sS0[g][wt] = g_esrc[p + wt]; sW0[g][wt] = g_ew[p + wt]; sE[g][wt] = g_eid[p + wt]; }
        bar_grp(g + 1);
        if (wt < cnt) {
            int my = sE[g][wt], rk = 0;
            for (int j = 0; j < cnt; j++) rk += (sE[g][j] < my);
            sSrc[g][rk] = sS0[g][wt]; sWt[g][rk] = sW0[g][wt];
        }
        bar_grp(g + 1);
        int i = 0;
        for (; i + 2 <= cnt; i += 2) {
            float w0 = sWt[g][i], w1 = sWt[g][i + 1];
            int s0 = sSrc[g][i] * 1024, s1 = sSrc[g][i + 1] * 1024;
            float4 l0 = *(const float4*)&g_H1[s0 + wt * 4];
            float4 h0 = *(const float4*)&g_H1[s0 + 512 + wt * 4];
            float4 l1 = *(const float4*)&g_H1[s1 + wt * 4];
            float4 h1 = *(const float4*)&g_H1[s1 + 512 + wt * 4];
            aLo.x += w0 * l0.x + w1 * l1.x;  aLo.y += w0 * l0.y + w1 * l1.y;
            aLo.z += w0 * l0.z + w1 * l1.z;  aLo.w += w0 * l0.w + w1 * l1.w;
            aHi.x += w0 * h0.x + w1 * h1.x;  aHi.y += w0 * h0.y + w1 * h1.y;
            aHi.z += w0 * h0.z + w1 * h1.z;  aHi.w += w0 * h0.w + w1 * h1.w;
        }
        if (i < cnt) {
            float w0 = sWt[g][i];
            int s0 = sSrc[g][i] * 1024;
            float4 l0 = *(const float4*)&g_H1[s0 + wt * 4];
            float4 h0 = *(const float4*)&g_H1[s0 + 512 + wt * 4];
            aLo.x += w0 * l0.x; aLo.y += w0 * l0.y; aLo.z += w0 * l0.z; aLo.w += w0 * l0.w;
            aHi.x += w0 * h0.x; aHi.y += w0 * h0.y; aHi.z += w0 * h0.z; aHi.w += w0 * h0.w;
        }
        bar_grp(g + 1);
    }
    *(float4*)&sAgg[g * 1024 + wt * 4]       = aLo;
    *(float4*)&sAgg[g * 1024 + 512 + wt * 4] = aHi;
    __syncthreads();

    int b = tid & 15, d = tid >> 4;            // d in 0..31 (also d+32)
    float h[8];
    float bi0 = b2[d], bi1 = b2[d + 32];
    #pragma unroll
    for (int gg = 0; gg < 4; gg++) { h[2 * gg] = bi0; h[2 * gg + 1] = bi1; }
    #pragma unroll 4
    for (int dd = 0; dd < D_DIM; dd++) {
        float w0 = sW[dd * 64 + d], w1 = sW[dd * 64 + d + 32];
        #pragma unroll
        for (int gg = 0; gg < 4; gg++) {
            float xa = sAgg[gg * 1024 + dd * 16 + b];
            h[2 * gg]     += xa * w0;
            h[2 * gg + 1] += xa * w1;
        }
    }
    int n0 = blockIdx.x * 4;
    #pragma unroll
    for (int gg = 0; gg < 4; gg++) {
        g_OBS[((n0 + gg) * 64 + d) * 16 + b]      = tanhf(h[2 * gg]);
        g_OBS[((n0 + gg) * 64 + d + 32) * 16 + b] = tanhf(h[2 * gg + 1]);
    }
}

// =================== launch 5: big GEMM (MLP=8 weight streaming) ===================
__global__ void __launch_bounds__(256, 3) k_big(const float* __restrict__ Wc,
                                                const float* __restrict__ Wa,
                                                const float* __restrict__ Wb) {
    __shared__ __align__(16) float sBuf[8192];        // 32KB
    unsigned long long* sBuf64 = (unsigned long long*)sBuf;

    int blk = blockIdx.x;
    const float* W; int ncols, segBlk, rows;
    if (blk < NBLK_C)               { W = Wc; ncols = 64;  segBlk = blk;            rows = 1280; }
    else if (blk < NBLK_C + NBLK_A) { W = Wa; ncols = 128; segBlk = blk - NBLK_C;   rows = 640; }
    else                            { W = Wb; ncols = 128; segBlk = blk - (NBLK_C + NBLK_A); rows = 640; }
    int k0 = segBlk * rows;

    const int tpr = ncols >> 1;        // threads per row: 32 or 64
    const int nrs = 256 / tpr;         // rows per step: 8 or 4
    int tid  = threadIdx.x;
    int slot = tid % tpr;
    int roff = tid / tpr;

    unsigned long long acc[16];
    #pragma unroll
    for (int i = 0; i < 16; i++) acc[i] = 0ULL;

    const int steps = 128 / nrs;       // 16 or 32
    for (int kt = k0; kt < k0 + rows; kt += 128) {
        const float4* src = (const float4*)(g_OBS + (size_t)kt * 16);
        float4* dst4 = (float4*)sBuf;
        dst4[tid]       = src[tid];
        dst4[tid + 256] = src[tid + 256];
        __syncthreads();

        for (int itg = 0; itg < steps; itg += 8) {
            float2 wv[8];
            #pragma unroll
            for (int u = 0; u < 8; u++) {
                int r = (itg + u) * nrs + roff;
                wv[u] = *(const float2*)(W + (size_t)(kt + r) * ncols + 2 * slot);
            }
            #pragma unroll
            for (int u = 0; u < 8; u++) {
                int r = (itg + u) * nrs + roff;
                unsigned long long wp0, wp1;
                asm("mov.b64 %0,{%1,%2};" : "=l"(wp0) : "f"(wv[u].x), "f"(wv[u].x));
                asm("mov.b64 %0,{%1,%2};" : "=l"(wp1) : "f"(wv[u].y), "f"(wv[u].y));
                const ulonglong2* ob2 = (const ulonglong2*)(sBuf64 + r * 8);
                #pragma unroll
                for (int q = 0; q < 4; q++) {
                    ulonglong2 op = ob2[q];
                    asm("fma.rn.f32x2 %0,%1,%2,%0;" : "+l"(acc[2*q])     : "l"(wp0), "l"(op.x));
                    asm("fma.rn.f32x2 %0,%1,%2,%0;" : "+l"(acc[2*q+1])   : "l"(wp0), "l"(op.y));
                    asm("fma.rn.f32x2 %0,%1,%2,%0;" : "+l"(acc[8+2*q])   : "l"(wp1), "l"(op.x));
                    asm("fma.rn.f32x2 %0,%1,%2,%0;" : "+l"(acc[8+2*q+1]) : "l"(wp1), "l"(op.y));
                }
            }
        }
        __syncthreads();
    }

    #pragma unroll
    for (int j = 0; j < 16; j++) sBuf64[tid * 16 + j] = acc[j];
    __syncthreads();
    for (int idx2 = tid; idx2 < tpr * 16; idx2 += 256) {
        int sIdx = idx2 >> 4, j = idx2 & 15;
        float lo = 0.f, hi = 0.f;
        for (int gq = 0; gq < nrs; gq++) {
            int base = ((gq * tpr + sIdx) * 16 + j) * 2;
            lo += sBuf[base];
            hi += sBuf[base + 1];
        }
        int col = 2 * sIdx + (j >> 3);
        int p = j & 7;
        g_part[blk * 2048 + (2 * p) * ncols + col]     = lo;
        g_part[blk * 2048 + (2 * p + 1) * ncols + col] = hi;
    }
}

// =================== launch 6: reduce partials ===================
__global__ void k_reduce(const float* __restrict__ bc1, const float* __restrict__ ba1,
                         const float* __restrict__ bb1) {
    __shared__ float red[8][33];
    int tid = threadIdx.x;               // 256
    int o_local = tid & 31, t8 = tid >> 5;
    int o = blockIdx.x * 32 + o_local;   // grid 160
    int blkBase, nblk, idx; float bias;
    if (o < 1024)      { blkBase = 0;               nblk = NBLK_C; idx = o;        bias = bc1[idx & 63]; }
    else if (o < 3072) { blkBase = NBLK_C;          nblk = NBLK_A; idx = o - 1024; bias = ba1[idx & 127]; }
    else               { blkBase = NBLK_C + NBLK_A; nblk = NBLK_B; idx = o - 3072; bias = bb1[idx & 127]; }
    float s = 0.f;
    for (int q = t8; q < nblk; q += 8) s += g_part[(size_t)(blkBase + q) * 2048 + idx];
    red[t8][o_local] = s;
    __syncthreads();
    if (t8 == 0) {
        float tot = bias;
        #pragma unroll
        for (int gq = 0; gq < 8; gq++) tot += red[gq][o_local];
        g_h1act[o] = tanhf(tot);
    }
}

// =================== launch 7: middle MLP layers ===================
__global__ void k_mid(const float* __restrict__ Wc2, const float* __restrict__ bc2,
                      const float* __restrict__ Wc3, const float* __restrict__ bc3,
                      const float* __restrict__ Wa2, const float* __restrict__ ba2,
                      const float* __restrict__ Wb2, const float* __restrict__ bb2,
                      float* __restrict__ out) {
    __shared__ float sH[2048];
    __shared__ float sH2[1024];
    int tid = threadIdx.x;               // 128 threads
    if (blockIdx.x == 0) {
        for (int i = tid; i < 1024; i += 128) sH[i] = g_h1act[i];
        __syncthreads();
        if (tid < 64) {
            int j = tid;
            float acc[16];
            #pragma unroll
            for (int b = 0; b < 16; b++) acc[b] = bc2[j];
            for (int k = 0; k < 64; k++) {
                float wv = Wc2[k * 64 + j];
                #pragma unroll
                for (int b = 0; b < 16; b++) acc[b] += sH[b * 64 + k] * wv;
            }
            #pragma unroll
            for (int b = 0; b < 16; b++) sH2[b * 64 + j] = tanhf(acc[b]);
        }
        __syncthreads();
        if (tid < 16) {
            float v = bc3[0];
            for (int j = 0; j < 64; j++) v += sH2[tid * 64 + j] * Wc3[j];
            out[240000 + tid] = v;
        }
    } else {
        const float* h1  = g_h1act + (blockIdx.x == 1 ? 1024 : 3072);
        const float* W2m = (blockIdx.x == 1 ? Wa2 : Wb2);
        const float* b2m = (blockIdx.x == 1 ? ba2 : bb2);
        float* dst       = (blockIdx.x == 1 ? g_ha2 : g_hb2);
        for (int i = tid; i < 2048; i += 128) sH[i] = h1[i];
        __syncthreads();
        int j = tid;
        float acc[16];
        #pragma unroll
        for (int b = 0; b < 16; b++) acc[b] = b2m[j];
        for (int k = 0; k < 128; k++) {
            float wv = W2m[k * 128 + j];
            #pragma unroll
            for (int b = 0; b < 16; b++) acc[b] += sH[b * 128 + k] * wv;
        }
        #pragma unroll
        for (int b = 0; b < 16; b++) dst[b * 128 + j] = tanhf(acc[b]);
    }
}

// =================== launch 8: heads + Beta distribution ===================
__device__ __forceinline__ float softplus_f(float z) {
    return fmaxf(z, 0.f) + log1pf(expf(-fabsf(z)));
}
__device__ __forceinline__ float psi_f(float x) {
    float r = 0.f;
    while (x < 6.f) { r -= 1.f / x; x += 1.f; }
    float xi = 1.f / x, xi2 = xi * xi;
    return r + logf(x) - 0.5f * xi
         - xi2 * (0.08333333333f - xi2 * (0.008333333333f - xi2 * 0.003968253968f));
}

__global__ void __launch_bounds__(128) k_final(const float* __restrict__ Wa3, const float* __restrict__ ba3,
                                               const float* __restrict__ Wb3, const float* __restrict__ bb3,
                                               float* __restrict__ out) {
    __shared__ float sA[2048], sB[2048];
    int tid = threadIdx.x;
    for (int i = tid; i < 2048; i += 128) { sA[i] = g_ha2[i]; sB[i] = g_hb2[i]; }
    __syncthreads();
    int n = blockIdx.x * 128 + tid;
    if (n >= N_NODES) return;

    float aA[16], aB[16];
    #pragma unroll
    for (int b = 0; b < 16; b++) { aA[b] = 0.f; aB[b] = 0.f; }
    for (int j = 0; j < 128; j++) {
        float wa = Wa3[j * N_NODES + n];
        float wb = Wb3[j * N_NODES + n];
        #pragma unroll
        for (int b = 0; b < 16; b++) {
            aA[b] += sA[b * 128 + j] * wa;
            aB[b] += sB[b * 128 + j] * wb;
        }
    }
    float bA = ba3[n], bB = bb3[n];
    #pragma unroll
    for (int b = 0; b < 16; b++) {
        float alpha = 1.f + softplus_f(aA[b] + bA);
        float beta  = 1.f + softplus_f(aB[b] + bB);
        float ab    = alpha + beta;
        float action = alpha / ab;
        float logB = lgammaf(alpha) + lgammaf(beta) - lgammaf(ab);
        float logp = (alpha - 1.f) * logf(action) + (beta - 1.f) * log1pf(-action) - logB;
        float ent  = logB - (alpha - 1.f) * psi_f(alpha) - (beta - 1.f) * psi_f(beta)
                   + (ab - 2.f) * psi_f(ab);
        out[b * N_NODES + n]           = action;
        out[80000 + b * N_NODES + n]   = logp;
        out[160000 + b * N_NODES + n]  = ent;
    }
}

// =================== launch 9: reset state for next replay ===================
__global__ void k_clean() {
    int i = blockIdx.x * blockDim.x + threadIdx.x;
    if (i < N_NODES) { g_deg[i] = 0; g_cur[i] = 0; }
}

// =================== launch ===================
extern "C" void kernel_launch(void* const* d_in, const int* in_sizes, int n_in,
                              void* d_out, int out_size) {
    const float* x   = (const float*)d_in[0];
    const int*   ei  = (const int*)  d_in[1];
    const float* W1  = (const float*)d_in[2];
    const float* b1  = (const float*)d_in[3];
    const float* W2  = (const float*)d_in[4];
    const float* b2  = (const float*)d_in[5];
    const float* Wc1 = (const float*)d_in[6];
    const float* bc1 = (const float*)d_in[7];
    const float* Wc2 = (const float*)d_in[8];
    const float* bc2 = (const float*)d_in[9];
    const float* Wc3 = (const float*)d_in[10];
    const float* bc3 = (const float*)d_in[11];
    const float* Wa1 = (const float*)d_in[12];
    const float* ba1 = (const float*)d_in[13];
    const float* Wa2 = (const float*)d_in[14];
    const float* ba2 = (const float*)d_in[15];
    const float* Wa3 = (const float*)d_in[16];
    const float* ba3 = (const float*)d_in[17];
    const float* Wb1 = (const float*)d_in[18];
    const float* bb1 = (const float*)d_in[19];
    const float* Wb2 = (const float*)d_in[20];
    const float* bb2 = (const float*)d_in[21];
    const float* Wb3 = (const float*)d_in[22];
    const float* bb3 = (const float*)d_in[23];
    float* out = (float*)d_out;

    const int E = in_sizes[1] / 2;   // 80000

    k_xtdeg<<<N_NODES, 512>>>(x, ei, E);                              // 0
    k_scan<<<1, 1024>>>(E + N_NODES);                                 // 1
    k_fill<<<(E + N_NODES + 255) / 256, 256>>>(ei, E);                // 2
    k_gcn1<<<N_NODES / 4, 512>>>(W1, b1);                             // 3  <- profiled
    k_gcn2<<<N_NODES / 4, 512>>>(W2, b2);                             // 4
    k_big<<<NBLK_BIG, 256>>>(Wc1, Wa1, Wb1);                          // 5
    k_reduce<<<160, 256>>>(bc1, ba1, bb1);                            // 6
    k_mid<<<3, 128>>>(Wc2, bc2, Wc3, bc3, Wa2, ba2, Wb2, bb2, out);   // 7
    k_final<<<(N_NODES + 127) / 128, 128>>>(Wa3, ba3, Wb3, bb3, out); // 8
    k_clean<<<(N_NODES + 255) / 256, 256>>>();                        // 9
}